// round 16
// baseline (speedup 1.0000x reference)
#include <cuda_runtime.h>
#include <cuda_fp16.h>
#include <cstdint>

// PowerSoftmax attention via warp-level mma.sync (HMMA) — base sm_103 PTX.
//   S = (Q K^T)/8 ; P = S^2 ; O = (P / (rowsum(P)+1e-6)) V
// 64 heads of [2048, 64] fp32.
//
// Single-fp16 operands (rel_err ~4.5e-4, measured R13).
// M=32 rows per warp (two m16 strips): every K/V B-fragment loaded by
// ldmatrix is reused by BOTH strips -> LDSM bytes per MMA halved (R14).
// CTA = 4 warps / 128 rows, launch_bounds(128,2) -> 2 CTAs/SM so one CTA's
// MMA hides the other's load/convert phases (restores R13's overlap).

#define NQ       2048
#define DDIM     64
#define BM       128
#define BKV      128
#define NITER    (NQ / BKV)
#define NTHREADS 128

// smem byte offsets
#define B_K   0              // K fp16 [128 rows x 64 cols = 128B/row]  16 KB
#define B_V   16384          // Vt[d][kv] fp16 [64 rows x 256B]         16 KB
#define SMEM_BYTES 32768
// Prologue borrows B_K for the Q fp16 image before the loop overwrites it.

// K/Q tiles: [rows][64 x 2B = 128B]
__device__ __forceinline__ uint32_t sw_q(int row, int cb) {
    return (uint32_t)(row * 128 + (cb ^ ((row & 7) << 4)));
}
// Vt tile: [64 rows][128 kv x 2B = 256B]
__device__ __forceinline__ uint32_t sw_v(int row, int cb) {
    return (uint32_t)(row * 256 + (cb ^ ((row & 7) << 4)));
}

__device__ __forceinline__ void ldsm_x4(uint32_t* r, uint32_t addr) {
    asm volatile("ldmatrix.sync.aligned.m8n8.x4.shared.b16 {%0,%1,%2,%3}, [%4];"
                 : "=r"(r[0]), "=r"(r[1]), "=r"(r[2]), "=r"(r[3]) : "r"(addr));
}
__device__ __forceinline__ void mma_f16(float* c, const uint32_t* a, const uint32_t* b) {
    asm volatile("mma.sync.aligned.m16n8k16.row.col.f32.f16.f16.f32 "
                 "{%0,%1,%2,%3}, {%4,%5,%6,%7}, {%8,%9}, {%0,%1,%2,%3};"
                 : "+f"(c[0]), "+f"(c[1]), "+f"(c[2]), "+f"(c[3])
                 : "r"(a[0]), "r"(a[1]), "r"(a[2]), "r"(a[3]), "r"(b[0]), "r"(b[1]));
}

__global__ __launch_bounds__(NTHREADS, 2)
void power_attn_hmma(const float* __restrict__ Q, const float* __restrict__ K,
                     const float* __restrict__ V, float* __restrict__ O) {
    extern __shared__ char sm[];
    const uint32_t smb = (uint32_t)__cvta_generic_to_shared(sm);

    const int tid  = threadIdx.x;
    const int lane = tid & 31;
    const int wid  = tid >> 5;
    const int mr0  = wid * 32;                 // warp's 32-row Q strip base

    const size_t head = (size_t)blockIdx.y * NQ * DDIM;
    const float* qb = Q + head + (size_t)blockIdx.x * BM * DDIM;
    const float* kb = K + head;
    const float* vb = V + head;

    // ---- Stage Q tile (128 rows) -> fp16 image in B_K (temporary) ----
    {
        const float4* qg = (const float4*)qb;
        #pragma unroll
        for (int p = 0; p < 16; ++p) {
            int idx = tid + p * NTHREADS;            // 0..2047 float4s
            int row = idx >> 4;
            int c8  = (idx & 15) * 8;
            float4 x = qg[idx];
            __half2 h01 = __floats2half2_rn(x.x, x.y);
            __half2 h23 = __floats2half2_rn(x.z, x.w);
            uint2 hh;
            hh.x = *(uint32_t*)&h01;
            hh.y = *(uint32_t*)&h23;
            *(uint2*)(sm + B_K + sw_q(row, c8)) = hh;
        }
    }
    __syncthreads();

    // ---- Hoist Q A-fragments (both strips) for the whole kernel ----
    uint32_t Qf[2][4][4];
    {
        const int a_row = mr0 + (lane & 15);
        const int a_cbo = (lane >> 4) << 4;          // +0 / +16B
        #pragma unroll
        for (int st = 0; st < 2; ++st)
            #pragma unroll
            for (int ks = 0; ks < 4; ++ks)
                ldsm_x4(Qf[st][ks], smb + B_K + sw_q(a_row + st * 16, ks * 32 + a_cbo));
    }

    float OC[2][8][4];                               // O accum per strip
    #pragma unroll
    for (int st = 0; st < 2; ++st)
        #pragma unroll
        for (int d = 0; d < 8; ++d)
            #pragma unroll
            for (int r = 0; r < 4; ++r) OC[st][d][r] = 0.f;
    float rs00 = 0.f, rs01 = 0.f, rs10 = 0.f, rs11 = 0.f;

    // x4 B-fragment lane addressing (2 blocks per load)
    const int bx_row = (lane & 7) + ((lane >> 4) << 3);
    const int bx_cbo = ((lane >> 3) & 1) << 4;

    const int vpart = tid >> 6;                      // V convert: kv half
    const int vd    = tid & 63;

    for (int nt = 0; nt < NITER; ++nt) {
        __syncthreads();                 // prev tile consumed (and Q hoisted)

        // ---- K tile (128 rows) -> fp16 image ----
        const float4* kg = (const float4*)(kb + (size_t)nt * BKV * DDIM);
        #pragma unroll
        for (int p = 0; p < 16; ++p) {
            int idx = tid + p * NTHREADS;
            int row = idx >> 4;
            int c8  = (idx & 15) * 8;
            float4 x = kg[idx];
            __half2 h01 = __floats2half2_rn(x.x, x.y);
            __half2 h23 = __floats2half2_rn(x.z, x.w);
            uint2 hh;
            hh.x = *(uint32_t*)&h01;
            hh.y = *(uint32_t*)&h23;
            *(uint2*)(sm + B_K + sw_q(row, c8)) = hh;
        }

        // ---- V tile -> Vt[d][kv] fp16 (transposed), uint2 stores ----
        {
            const float* vg = vb + (size_t)nt * BKV * DDIM;
            #pragma unroll
            for (int i = 0; i < 16; ++i) {
                int kv = vpart * 64 + i * 4;
                float x0 = vg[(size_t)(kv + 0) * DDIM + vd];
                float x1 = vg[(size_t)(kv + 1) * DDIM + vd];
                float x2 = vg[(size_t)(kv + 2) * DDIM + vd];
                float x3 = vg[(size_t)(kv + 3) * DDIM + vd];
                __half2 ha = __floats2half2_rn(x0, x1);
                __half2 hb = __floats2half2_rn(x2, x3);
                uint2 u;
                u.x = *(uint32_t*)&ha;
                u.y = *(uint32_t*)&hb;
                *(uint2*)(sm + B_V + sw_v(vd, kv * 2)) = u;
            }
        }
        __syncthreads();

        // ---- Fused QK -> square -> PV, chunked by 16 kv columns ----
        #pragma unroll
        for (int h = 0; h < 2; ++h) {                // kv halves of 64
            #pragma unroll
            for (int ch = 0; ch < 4; ++ch) {         // chunks: 2 n-blocks
                float SC[2][2][4];
                #pragma unroll
                for (int st = 0; st < 2; ++st)
                    #pragma unroll
                    for (int j = 0; j < 2; ++j)
                        #pragma unroll
                        for (int r = 0; r < 4; ++r) SC[st][j][r] = 0.f;

                int n0 = h * 64 + ch * 16;
                #pragma unroll
                for (int ks = 0; ks < 4; ++ks) {
                    uint32_t Bh[4];
                    ldsm_x4(Bh, smb + B_K + sw_q(n0 + bx_row, ks * 32 + bx_cbo));
                    #pragma unroll
                    for (int st = 0; st < 2; ++st) {
                        mma_f16(SC[st][0], Qf[st][ks], Bh + 0);
                        mma_f16(SC[st][1], Qf[st][ks], Bh + 2);
                    }
                }

                // p = (s/8)^2 -> fp16 A-fragment for this 16-kv chunk
                uint32_t P[2][4];
                #pragma unroll
                for (int st = 0; st < 2; ++st) {
                    float s0 = SC[st][0][0] * 0.125f, s1 = SC[st][0][1] * 0.125f;
                    float s2 = SC[st][0][2] * 0.125f, s3 = SC[st][0][3] * 0.125f;
                    float t0 = SC[st][1][0] * 0.125f, t1 = SC[st][1][1] * 0.125f;
                    float t2 = SC[st][1][2] * 0.125f, t3 = SC[st][1][3] * 0.125f;
                    __half2 a0 = __floats2half2_rn(s0 * s0, s1 * s1);
                    __half2 a1 = __floats2half2_rn(s2 * s2, s3 * s3);
                    __half2 a2 = __floats2half2_rn(t0 * t0, t1 * t1);
                    __half2 a3 = __floats2half2_rn(t2 * t2, t3 * t3);
                    float2 f0 = __half22float2(a0);
                    float2 f1 = __half22float2(a1);
                    float2 f2 = __half22float2(a2);
                    float2 f3 = __half22float2(a3);
                    if (st == 0) {
                        rs00 += f0.x + f0.y + f2.x + f2.y;
                        rs01 += f1.x + f1.y + f3.x + f3.y;
                    } else {
                        rs10 += f0.x + f0.y + f2.x + f2.y;
                        rs11 += f1.x + f1.y + f3.x + f3.y;
                    }
                    P[st][0] = *(uint32_t*)&a0;
                    P[st][1] = *(uint32_t*)&a1;
                    P[st][2] = *(uint32_t*)&a2;
                    P[st][3] = *(uint32_t*)&a3;
                }

                // O += P V for this chunk (Bv shared by both strips)
                int kvb = n0 * 2 + bx_cbo;           // byte col in Vt row
                #pragma unroll
                for (int dp = 0; dp < 4; ++dp) {
                    uint32_t Bv[4];
                    ldsm_x4(Bv, smb + B_V + sw_v(dp * 16 + bx_row, kvb));
                    #pragma unroll
                    for (int st = 0; st < 2; ++st) {
                        mma_f16(OC[st][2 * dp],     P[st], Bv + 0);
                        mma_f16(OC[st][2 * dp + 1], P[st], Bv + 2);
                    }
                }
            }
        }
    }

    // ---- Rowsum reduce across the 4 lanes of each row group ----
    rs00 += __shfl_xor_sync(0xFFFFFFFF, rs00, 1);
    rs00 += __shfl_xor_sync(0xFFFFFFFF, rs00, 2);
    rs01 += __shfl_xor_sync(0xFFFFFFFF, rs01, 1);
    rs01 += __shfl_xor_sync(0xFFFFFFFF, rs01, 2);
    rs10 += __shfl_xor_sync(0xFFFFFFFF, rs10, 1);
    rs10 += __shfl_xor_sync(0xFFFFFFFF, rs10, 2);
    rs11 += __shfl_xor_sync(0xFFFFFFFF, rs11, 1);
    rs11 += __shfl_xor_sync(0xFFFFFFFF, rs11, 2);

    // ---- Store O (both strips) ----
    {
        const float inv[2][2] = {
            {1.0f / (rs00 + 1e-6f), 1.0f / (rs01 + 1e-6f)},
            {1.0f / (rs10 + 1e-6f), 1.0f / (rs11 + 1e-6f)}
        };
        #pragma unroll
        for (int st = 0; st < 2; ++st) {
            const int row0 = mr0 + st * 16 + (lane >> 2);
            float* ob = O + head + ((size_t)blockIdx.x * BM + row0) * DDIM;
            #pragma unroll
            for (int db = 0; db < 8; ++db) {
                int col = db * 8 + (lane & 3) * 2;
                float2 t0 = make_float2(OC[st][db][0] * inv[st][0],
                                        OC[st][db][1] * inv[st][0]);
                float2 t1 = make_float2(OC[st][db][2] * inv[st][1],
                                        OC[st][db][3] * inv[st][1]);
                *(float2*)(ob + col) = t0;
                *(float2*)(ob + 8 * DDIM + col) = t1;
            }
        }
    }
}

extern "C" void kernel_launch(void* const* d_in, const int* in_sizes, int n_in,
                              void* d_out, int out_size) {
    const float* q = (const float*)d_in[0];
    const float* k = (const float*)d_in[1];
    const float* v = (const float*)d_in[2];
    float* o = (float*)d_out;

    const int BH = in_sizes[0] / (NQ * DDIM);   // 64 heads

    cudaFuncSetAttribute(power_attn_hmma,
                         cudaFuncAttributeMaxDynamicSharedMemorySize, SMEM_BYTES);

    dim3 grid(NQ / BM, BH);
    power_attn_hmma<<<grid, NTHREADS, SMEM_BYTES>>>(q, k, v, o);
}

// round 17
// speedup vs baseline: 1.1134x; 1.1134x over previous
#include <cuda_runtime.h>
#include <cuda_fp16.h>
#include <cstdint>

// PowerSoftmax attention via warp-level mma.sync (HMMA) — base sm_103 PTX.
//   S = (Q K^T)/8 ; P = S^2 ; O = (P / (rowsum(P)+1e-6)) V
// 64 heads of [2048, 64] fp32.
//
// R13 structure (M=16/warp, 256 thr, 2 CTAs/SM = 16 warps/SM) + DOUBLE-
// BUFFERED K/V smem: one barrier per iteration; loads for tile nt+1 are
// interleaved with compute of tile nt so LDG latency hides under MMA
// instead of serializing at a barrier.
// Single-fp16 operands (rel_err ~4.5e-4, measured R13).

#define NQ       2048
#define DDIM     64
#define BM       128
#define BKV      128
#define NITER    (NQ / BKV)
#define NTHREADS 256

// per-buffer layout: K at +0 (16 KB), Vt at +16384 (16 KB); two buffers
#define B_V      16384
#define BUFSZ    32768
#define SMEM_BYTES 65536
// Prologue borrows buf0's K area for the Q fp16 image.

// K/Q tiles: [rows][64 x 2B = 128B]
__device__ __forceinline__ uint32_t sw_q(int row, int cb) {
    return (uint32_t)(row * 128 + (cb ^ ((row & 7) << 4)));
}
// Vt tile: [64 rows][128 kv x 2B = 256B]
__device__ __forceinline__ uint32_t sw_v(int row, int cb) {
    return (uint32_t)(row * 256 + (cb ^ ((row & 7) << 4)));
}

__device__ __forceinline__ void ldsm_x4(uint32_t* r, uint32_t addr) {
    asm volatile("ldmatrix.sync.aligned.m8n8.x4.shared.b16 {%0,%1,%2,%3}, [%4];"
                 : "=r"(r[0]), "=r"(r[1]), "=r"(r[2]), "=r"(r[3]) : "r"(addr));
}
__device__ __forceinline__ void mma_f16(float* c, const uint32_t* a, const uint32_t* b) {
    asm volatile("mma.sync.aligned.m16n8k16.row.col.f32.f16.f16.f32 "
                 "{%0,%1,%2,%3}, {%4,%5,%6,%7}, {%8,%9}, {%0,%1,%2,%3};"
                 : "+f"(c[0]), "+f"(c[1]), "+f"(c[2]), "+f"(c[3])
                 : "r"(a[0]), "r"(a[1]), "r"(a[2]), "r"(a[3]), "r"(b[0]), "r"(b[1]));
}

__global__ __launch_bounds__(NTHREADS, 2)
void power_attn_hmma(const float* __restrict__ Q, const float* __restrict__ K,
                     const float* __restrict__ V, float* __restrict__ O) {
    extern __shared__ char sm[];
    const uint32_t smb = (uint32_t)__cvta_generic_to_shared(sm);

    const int tid  = threadIdx.x;
    const int lane = tid & 31;
    const int wid  = tid >> 5;
    const int mr   = wid * 16;                 // warp's 16-row Q strip

    const size_t head = (size_t)blockIdx.y * NQ * DDIM;
    const float* qb = Q + head + (size_t)blockIdx.x * BM * DDIM;
    const float* kb = K + head;
    const float* vb = V + head;

    const int vpart = tid >> 6;                      // V convert: kv quarter
    const int vd    = tid & 63;

    // ---- Stage Q tile -> fp16 image in buf0 K area (temporary) ----
    {
        const float4* qg = (const float4*)qb;
        #pragma unroll
        for (int p = 0; p < 8; ++p) {
            int idx = tid + p * NTHREADS;            // 0..2047 float4s
            int row = idx >> 4;
            int c8  = (idx & 15) * 8;
            float4 x = qg[idx];
            __half2 h01 = __floats2half2_rn(x.x, x.y);
            __half2 h23 = __floats2half2_rn(x.z, x.w);
            uint2 hh;
            hh.x = *(uint32_t*)&h01;
            hh.y = *(uint32_t*)&h23;
            *(uint2*)(sm + sw_q(row, c8)) = hh;
        }
    }
    __syncthreads();

    // ---- Hoist Q A-fragments for the whole kernel ----
    uint32_t Qf[4][4];
    {
        const int a_row = mr + (lane & 15);
        const int a_cbo = (lane >> 4) << 4;          // +0 / +16B
        #pragma unroll
        for (int ks = 0; ks < 4; ++ks)
            ldsm_x4(Qf[ks], smb + sw_q(a_row, ks * 32 + a_cbo));
    }
    __syncthreads();                                 // Q image free for reuse

    // ---- Load tile 0 into buf0 ----
    {
        const float4* kg = (const float4*)kb;
        #pragma unroll
        for (int p = 0; p < 8; ++p) {
            int idx = tid + p * NTHREADS;
            int row = idx >> 4;
            int c8  = (idx & 15) * 8;
            float4 x = kg[idx];
            __half2 h01 = __floats2half2_rn(x.x, x.y);
            __half2 h23 = __floats2half2_rn(x.z, x.w);
            uint2 hh;
            hh.x = *(uint32_t*)&h01;
            hh.y = *(uint32_t*)&h23;
            *(uint2*)(sm + sw_q(row, c8)) = hh;
        }
        #pragma unroll
        for (int i = 0; i < 8; ++i) {
            int kv = vpart * 32 + i * 4;
            float x0 = vb[(size_t)(kv + 0) * DDIM + vd];
            float x1 = vb[(size_t)(kv + 1) * DDIM + vd];
            float x2 = vb[(size_t)(kv + 2) * DDIM + vd];
            float x3 = vb[(size_t)(kv + 3) * DDIM + vd];
            __half2 ha = __floats2half2_rn(x0, x1);
            __half2 hb = __floats2half2_rn(x2, x3);
            uint2 u;
            u.x = *(uint32_t*)&ha;
            u.y = *(uint32_t*)&hb;
            *(uint2*)(sm + B_V + sw_v(vd, kv * 2)) = u;
        }
    }

    float OC[8][4];                                  // O accum: 8 d-blocks
    #pragma unroll
    for (int d = 0; d < 8; ++d)
        #pragma unroll
        for (int r = 0; r < 4; ++r) OC[d][r] = 0.f;
    float rs0 = 0.f, rs1 = 0.f;                      // rowsum (rows l/4, l/4+8)

    // x4 B-fragment lane addressing (2 n-blocks per load)
    const int bx_row = (lane & 7) + ((lane >> 4) << 3);
    const int bx_cbo = ((lane >> 3) & 1) << 4;

    for (int nt = 0; nt < NITER; ++nt) {
        __syncthreads();        // buf[cur] fully written (STS from all warps)
        const uint32_t cur = smb + (uint32_t)(nt & 1) * BUFSZ;
        const uint32_t nxt = smb + (uint32_t)((nt + 1) & 1) * BUFSZ;
        char* nxp = sm + (size_t)((nt + 1) & 1) * BUFSZ;

        // ---- K(nt+1) -> buf[nxt] (overlaps with compute below) ----
        if (nt + 1 < NITER) {
            const float4* kg = (const float4*)(kb + (size_t)(nt + 1) * BKV * DDIM);
            #pragma unroll
            for (int p = 0; p < 8; ++p) {
                int idx = tid + p * NTHREADS;
                int row = idx >> 4;
                int c8  = (idx & 15) * 8;
                float4 x = kg[idx];
                __half2 h01 = __floats2half2_rn(x.x, x.y);
                __half2 h23 = __floats2half2_rn(x.z, x.w);
                uint2 hh;
                hh.x = *(uint32_t*)&h01;
                hh.y = *(uint32_t*)&h23;
                *(uint2*)(nxp + sw_q(row, c8)) = hh;
            }
        }

        // ---- Compute h = 0 (kv 0..63 of cur tile) ----
        #pragma unroll
        for (int h = 0; h < 1; ++h) {}               // (kept for clarity)
        {
            const int h = 0;
            float SC[8][4];
            #pragma unroll
            for (int nb = 0; nb < 8; ++nb)
                #pragma unroll
                for (int r = 0; r < 4; ++r) SC[nb][r] = 0.f;

            #pragma unroll
            for (int ks = 0; ks < 4; ++ks) {
                #pragma unroll
                for (int p = 0; p < 4; ++p) {
                    int n0 = h * 64 + p * 16;
                    uint32_t Bh[4];
                    ldsm_x4(Bh, cur + sw_q(n0 + bx_row, ks * 32 + bx_cbo));
                    mma_f16(SC[2 * p],     Qf[ks], Bh + 0);
                    mma_f16(SC[2 * p + 1], Qf[ks], Bh + 2);
                }
            }

            uint32_t P[4][4];
            #pragma unroll
            for (int nb = 0; nb < 8; ++nb) {
                float s0 = SC[nb][0] * 0.125f, s1 = SC[nb][1] * 0.125f;
                float s2 = SC[nb][2] * 0.125f, s3 = SC[nb][3] * 0.125f;
                __half2 h01 = __floats2half2_rn(s0 * s0, s1 * s1);
                __half2 h23 = __floats2half2_rn(s2 * s2, s3 * s3);
                float2 f01 = __half22float2(h01);
                float2 f23 = __half22float2(h23);
                rs0 += f01.x + f01.y;
                rs1 += f23.x + f23.y;
                int kk = nb >> 1, hi = (nb & 1) * 2;
                P[kk][hi + 0] = *(uint32_t*)&h01;
                P[kk][hi + 1] = *(uint32_t*)&h23;
            }

            #pragma unroll
            for (int kk = 0; kk < 4; ++kk) {
                int kvb = (h * 64 + kk * 16) * 2 + bx_cbo;
                #pragma unroll
                for (int dp = 0; dp < 4; ++dp) {
                    uint32_t Bv[4];
                    ldsm_x4(Bv, cur + B_V + sw_v(dp * 16 + bx_row, kvb));
                    mma_f16(OC[2 * dp],     P[kk], Bv + 0);
                    mma_f16(OC[2 * dp + 1], P[kk], Bv + 2);
                }
            }
        }

        // ---- V(nt+1) -> buf[nxt] (overlaps with compute below) ----
        if (nt + 1 < NITER) {
            const float* vg = vb + (size_t)(nt + 1) * BKV * DDIM;
            #pragma unroll
            for (int i = 0; i < 8; ++i) {
                int kv = vpart * 32 + i * 4;
                float x0 = vg[(size_t)(kv + 0) * DDIM + vd];
                float x1 = vg[(size_t)(kv + 1) * DDIM + vd];
                float x2 = vg[(size_t)(kv + 2) * DDIM + vd];
                float x3 = vg[(size_t)(kv + 3) * DDIM + vd];
                __half2 ha = __floats2half2_rn(x0, x1);
                __half2 hb = __floats2half2_rn(x2, x3);
                uint2 u;
                u.x = *(uint32_t*)&ha;
                u.y = *(uint32_t*)&hb;
                *(uint2*)(nxp + B_V + sw_v(vd, kv * 2)) = u;
            }
        }

        // ---- Compute h = 1 (kv 64..127 of cur tile) ----
        {
            const int h = 1;
            float SC[8][4];
            #pragma unroll
            for (int nb = 0; nb < 8; ++nb)
                #pragma unroll
                for (int r = 0; r < 4; ++r) SC[nb][r] = 0.f;

            #pragma unroll
            for (int ks = 0; ks < 4; ++ks) {
                #pragma unroll
                for (int p = 0; p < 4; ++p) {
                    int n0 = h * 64 + p * 16;
                    uint32_t Bh[4];
                    ldsm_x4(Bh, cur + sw_q(n0 + bx_row, ks * 32 + bx_cbo));
                    mma_f16(SC[2 * p],     Qf[ks], Bh + 0);
                    mma_f16(SC[2 * p + 1], Qf[ks], Bh + 2);
                }
            }

            uint32_t P[4][4];
            #pragma unroll
            for (int nb = 0; nb < 8; ++nb) {
                float s0 = SC[nb][0] * 0.125f, s1 = SC[nb][1] * 0.125f;
                float s2 = SC[nb][2] * 0.125f, s3 = SC[nb][3] * 0.125f;
                __half2 h01 = __floats2half2_rn(s0 * s0, s1 * s1);
                __half2 h23 = __floats2half2_rn(s2 * s2, s3 * s3);
                float2 f01 = __half22float2(h01);
                float2 f23 = __half22float2(h23);
                rs0 += f01.x + f01.y;
                rs1 += f23.x + f23.y;
                int kk = nb >> 1, hi = (nb & 1) * 2;
                P[kk][hi + 0] = *(uint32_t*)&h01;
                P[kk][hi + 1] = *(uint32_t*)&h23;
            }

            #pragma unroll
            for (int kk = 0; kk < 4; ++kk) {
                int kvb = (h * 64 + kk * 16) * 2 + bx_cbo;
                #pragma unroll
                for (int dp = 0; dp < 4; ++dp) {
                    uint32_t Bv[4];
                    ldsm_x4(Bv, cur + B_V + sw_v(dp * 16 + bx_row, kvb));
                    mma_f16(OC[2 * dp],     P[kk], Bv + 0);
                    mma_f16(OC[2 * dp + 1], P[kk], Bv + 2);
                }
            }
        }
    }

    // ---- Rowsum reduce across the 4 lanes of each row group ----
    rs0 += __shfl_xor_sync(0xFFFFFFFF, rs0, 1);
    rs0 += __shfl_xor_sync(0xFFFFFFFF, rs0, 2);
    rs1 += __shfl_xor_sync(0xFFFFFFFF, rs1, 1);
    rs1 += __shfl_xor_sync(0xFFFFFFFF, rs1, 2);
    const float inv0 = 1.0f / (rs0 + 1e-6f);
    const float inv1 = 1.0f / (rs1 + 1e-6f);

    // ---- Store O ----
    {
        const int row0 = mr + (lane >> 2);
        float* ob = O + head + ((size_t)blockIdx.x * BM + row0) * DDIM;
        #pragma unroll
        for (int db = 0; db < 8; ++db) {
            int col = db * 8 + (lane & 3) * 2;
            float2 t0 = make_float2(OC[db][0] * inv0, OC[db][1] * inv0);
            float2 t1 = make_float2(OC[db][2] * inv1, OC[db][3] * inv1);
            *(float2*)(ob + col) = t0;
            *(float2*)(ob + 8 * DDIM + col) = t1;
        }
    }
}

extern "C" void kernel_launch(void* const* d_in, const int* in_sizes, int n_in,
                              void* d_out, int out_size) {
    const float* q = (const float*)d_in[0];
    const float* k = (const float*)d_in[1];
    const float* v = (const float*)d_in[2];
    float* o = (float*)d_out;

    const int BH = in_sizes[0] / (NQ * DDIM);   // 64 heads

    cudaFuncSetAttribute(power_attn_hmma,
                         cudaFuncAttributeMaxDynamicSharedMemorySize, SMEM_BYTES);

    dim3 grid(NQ / BM, BH);
    power_attn_hmma<<<grid, NTHREADS, SMEM_BYTES>>>(q, k, v, o);
}